// round 10
// baseline (speedup 1.0000x reference)
#include <cuda_runtime.h>
#include <cuda_bf16.h>
#include <cstdint>

#define Bb 8
#define Nn 1024
#define Cc 1024
#define Hh 16
#define Dd 64
#define NDh (Nn * Dd)

// ---------------- scratch (device globals; allocation-free) ----------------
__device__ __align__(16) __nv_bfloat16 g_xh[Bb * Nn * Cc], g_xl[Bb * Nn * Cc];
__device__ __align__(16) __nv_bfloat16 g_wih[3 * Cc * Cc], g_wil[3 * Cc * Cc];
__device__ __align__(16) __nv_bfloat16 g_woh[Cc * Cc], g_wol[Cc * Cc];
__device__ __align__(16) __nv_bfloat16 g_qh[Bb * Hh * NDh], g_ql[Bb * Hh * NDh];
__device__ __align__(16) __nv_bfloat16 g_kh[Bb * Hh * NDh], g_kl[Bb * Hh * NDh];
__device__ __align__(16) __nv_bfloat16 g_vh[Bb * Hh * NDh], g_vl[Bb * Hh * NDh];
__device__ __align__(16) __nv_bfloat16 g_aoh[Bb * Nn * Cc], g_aol[Bb * Nn * Cc];

// ---------------------------- PTX helpers ----------------------------------
#define LDSM4(r0, r1, r2, r3, addr)                                          \
    asm volatile("ldmatrix.sync.aligned.m8n8.x4.shared.b16 {%0,%1,%2,%3},[%4];" \
                 : "=r"(r0), "=r"(r1), "=r"(r2), "=r"(r3) : "r"(addr))
#define LDSM4T(r0, r1, r2, r3, addr)                                         \
    asm volatile("ldmatrix.sync.aligned.m8n8.x4.trans.shared.b16 {%0,%1,%2,%3},[%4];" \
                 : "=r"(r0), "=r"(r1), "=r"(r2), "=r"(r3) : "r"(addr))
#define MMA16816(c, a, b)                                                    \
    asm volatile("mma.sync.aligned.m16n8k16.row.col.f32.bf16.bf16.f32 "      \
                 "{%0,%1,%2,%3},{%4,%5,%6,%7},{%8,%9},{%0,%1,%2,%3};"        \
                 : "+f"((c)[0]), "+f"((c)[1]), "+f"((c)[2]), "+f"((c)[3])    \
                 : "r"((a)[0]), "r"((a)[1]), "r"((a)[2]), "r"((a)[3]),       \
                   "r"((b)[0]), "r"((b)[1]))
#define CP_ASYNC16(dst, src)                                                 \
    asm volatile("cp.async.cg.shared.global [%0],[%1],16;" :: "r"(dst), "l"(src))
#define CP_COMMIT() asm volatile("cp.async.commit_group;")
#define CP_WAIT1()  asm volatile("cp.async.wait_group 1;")
#define CP_WAIT0()  asm volatile("cp.async.wait_group 0;")

__device__ __forceinline__ uint32_t packbf(float lo, float hi) {
    uint32_t r;
    asm("cvt.rn.bf16x2.f32 %0,%1,%2;" : "=r"(r) : "f"(hi), "f"(lo));
    return r;
}
__device__ __forceinline__ void split2(float v0, float v1,
                                       uint32_t& hi, uint32_t& lo) {
    __nv_bfloat16 h0 = __float2bfloat16(v0), h1 = __float2bfloat16(v1);
    hi = ((uint32_t)__bfloat16_as_ushort(h1) << 16) | __bfloat16_as_ushort(h0);
    lo = packbf(v0 - __bfloat162float(h0), v1 - __bfloat162float(h1));
}

// ------------------------- fp32 -> bf16 hi/lo split -------------------------
__global__ __launch_bounds__(256) void cvt_kernel(const float4* __restrict__ in,
                                                  int which, int n4)
{
    int i = blockIdx.x * 256 + threadIdx.x;
    if (i >= n4) return;
    __nv_bfloat16 *hi, *lo;
    if (which == 0)      { hi = g_xh;  lo = g_xl;  }
    else if (which == 1) { hi = g_wih; lo = g_wil; }
    else                 { hi = g_woh; lo = g_wol; }
    float4 f = in[i];
    uint32_t h01, l01, h23, l23;
    split2(f.x, f.y, h01, l01);
    split2(f.z, f.w, h23, l23);
    ((uint2*)hi)[i] = make_uint2(h01, h23);
    ((uint2*)lo)[i] = make_uint2(l01, l23);
}

// ---------------------------------------------------------------------------
// bf16x3 TN GEMM (HMMA): C[m,n] = sum_k A[m,k]*W[n,k] + bias[n]
// CTA tile 128x128, BK=32, 3-stage cp.async, ONE __syncthreads per chunk.
// SW64-style swizzle (64B rows, 16B unit ^= (row>>1)&3) instead of padding:
// stage = 4 x 8KB = 32KB; 3 stages = 96KB -> still 2 CTAs/SM.
// 8 warps (4m x 2n), warp tile 32x64, __launch_bounds__(256,2).
// acc += Ah*Wh + Ah*Wl + Al*Wh (fp32 MMA accumulators).
// ---------------------------------------------------------------------------
#define MATG 8192                    // 128 rows x 64 B
#define GSTG (4 * MATG)              // 32768 B / stage
#define GSMEM (3 * GSTG)             // 98304 B

// swizzled byte offset within one matrix tile
#define SWOFF(row, unit) ((uint32_t)((row) * 64 + (((unit) ^ (((row) >> 1) & 3)) << 4)))

template <int EPI>
__device__ __forceinline__ void tg_load(uint32_t sbase, int bm, int bn,
                                        int k0, int tid)
{
    const __nv_bfloat16* Ah = (EPI == 0) ? g_xh : g_aoh;
    const __nv_bfloat16* Al = (EPI == 0) ? g_xl : g_aol;
    const __nv_bfloat16* Wh = (EPI == 0) ? g_wih : g_woh;
    const __nv_bfloat16* Wl = (EPI == 0) ? g_wil : g_wol;
#pragma unroll
    for (int u = 0; u < 2; u++) {
        int idx = u * 256 + tid;          // 0..511
        int row = idx >> 2, un = idx & 3;
        uint32_t soff = SWOFF(row, un);
        size_t ga = (size_t)(bm + row) * 1024 + k0 + un * 8;
        size_t gw = (size_t)(bn + row) * 1024 + k0 + un * 8;
        CP_ASYNC16(sbase + 0 * MATG + soff, Ah + ga);
        CP_ASYNC16(sbase + 1 * MATG + soff, Al + ga);
        CP_ASYNC16(sbase + 2 * MATG + soff, Wh + gw);
        CP_ASYNC16(sbase + 3 * MATG + soff, Wl + gw);
    }
}

template <int EPI>
__global__ __launch_bounds__(256, 2) void gemm_mma(const float* __restrict__ bias,
                                                   float* __restrict__ out)
{
    extern __shared__ __align__(16) char smem[];
    const uint32_t sm0 = (uint32_t)__cvta_generic_to_shared(smem);

    const int tid  = threadIdx.x;
    const int lane = tid & 31;
    const int wid  = tid >> 5;
    const int wm = (wid & 3) * 32;     // warp m offset (4 groups)
    const int wn = (wid >> 2) * 64;    // warp n offset (2 groups)
    const int bm = blockIdx.y * 128;
    const int bn = blockIdx.x * 128;

    // ldmatrix lane geometry
    const int lr = lane & 7, lq = lane >> 3;
    const int arow = wm + (lq & 1) * 8 + lr;            // + im*16 (sx invariant)
    const int sxA  = ((arow >> 1) & 3);
    const int aub  = (lq >> 1);                         // unit bit0; bit1 = ks
    const int brow = wn + (lane & 7) + ((lane >> 4) & 1) * 8;  // + jn2*16
    const int sxB  = ((brow >> 1) & 3);
    const int bub  = ((lane >> 3) & 1);

    float c[2][8][4];
#pragma unroll
    for (int im = 0; im < 2; im++)
#pragma unroll
        for (int jn = 0; jn < 8; jn++)
#pragma unroll
            for (int q = 0; q < 4; q++) c[im][jn][q] = 0.0f;

    tg_load<EPI>(sm0 + 0 * GSTG, bm, bn, 0, tid);
    CP_COMMIT();
    tg_load<EPI>(sm0 + 1 * GSTG, bm, bn, 32, tid);
    CP_COMMIT();

    for (int ch = 0; ch < 32; ch++) {
        if (ch < 31) CP_WAIT1(); else CP_WAIT0();
        __syncthreads();               // stage ch%3 ready; oldest buffer free

        if (ch < 30) {                 // prefetch ch+2 into buffer (ch+2)%3
            tg_load<EPI>(sm0 + ((ch + 2) % 3) * GSTG, bm, bn, (ch + 2) * 32, tid);
            CP_COMMIT();
        }

        const uint32_t st = sm0 + (ch % 3) * GSTG;
        const uint32_t tAh = st, tAl = st + MATG;
        const uint32_t tBh = st + 2 * MATG, tBl = st + 3 * MATG;

#pragma unroll
        for (int ks = 0; ks < 2; ks++) {
            const uint32_t aup = (uint32_t)((((ks << 1) | aub) ^ sxA) << 4);
            const uint32_t bup = (uint32_t)((((ks << 1) | bub) ^ sxB) << 4);
            uint32_t aH[2][4], aL[2][4];
#pragma unroll
            for (int im = 0; im < 2; im++) {
                uint32_t off = (uint32_t)((arow + im * 16) * 64) + aup;
                LDSM4(aH[im][0], aH[im][1], aH[im][2], aH[im][3], tAh + off);
                LDSM4(aL[im][0], aL[im][1], aL[im][2], aL[im][3], tAl + off);
            }
#pragma unroll
            for (int jn2 = 0; jn2 < 4; jn2++) {
                uint32_t bh[4], bl[4];
                uint32_t off = (uint32_t)((brow + jn2 * 16) * 64) + bup;
                LDSM4(bh[0], bh[1], bh[2], bh[3], tBh + off);
                LDSM4(bl[0], bl[1], bl[2], bl[3], tBl + off);
                // interleave across 4 independent accumulators
#pragma unroll
                for (int im = 0; im < 2; im++) {
                    MMA16816(c[im][2 * jn2],     aH[im], &bh[0]);
                    MMA16816(c[im][2 * jn2 + 1], aH[im], &bh[2]);
                }
#pragma unroll
                for (int im = 0; im < 2; im++) {
                    MMA16816(c[im][2 * jn2],     aH[im], &bl[0]);
                    MMA16816(c[im][2 * jn2 + 1], aH[im], &bl[2]);
                }
#pragma unroll
                for (int im = 0; im < 2; im++) {
                    MMA16816(c[im][2 * jn2],     aL[im], &bh[0]);
                    MMA16816(c[im][2 * jn2 + 1], aL[im], &bh[2]);
                }
            }
        }
    }

    // epilogue
#pragma unroll
    for (int im = 0; im < 2; im++) {
#pragma unroll
        for (int jn = 0; jn < 8; jn++) {
            int r0 = bm + wm + im * 16 + (lane >> 2);
            int cg = bn + wn + jn * 8 + 2 * (lane & 3);
            float b0 = bias[cg], b1 = bias[cg + 1];
#pragma unroll
            for (int half = 0; half < 2; half++) {
                int r = r0 + half * 8;
                float v0 = c[im][jn][half * 2 + 0] + b0;
                float v1 = c[im][jn][half * 2 + 1] + b1;
                if (EPI == 0) {
                    int b = r >> 10, nn = r & 1023;
                    int s = cg >> 10;
                    int h = (cg >> 6) & 15;
                    int d = cg & 63;
                    if (s == 0) { v0 *= 0.125f; v1 *= 0.125f; }  // fold QK scale
                    __nv_bfloat16 *hiA = (s == 0) ? g_qh : (s == 1) ? g_kh : g_vh;
                    __nv_bfloat16 *loA = (s == 0) ? g_ql : (s == 1) ? g_kl : g_vl;
                    size_t idx = (((size_t)b * Hh + h) * Nn + nn) * Dd + d;
                    uint32_t hp, lp;
                    split2(v0, v1, hp, lp);
                    *(uint32_t*)&hiA[idx] = hp;
                    *(uint32_t*)&loA[idx] = lp;
                } else {
                    *(float2*)&out[(size_t)r * 1024 + cg] = make_float2(v0, v1);
                }
            }
        }
    }
}

// ---------------------------------------------------------------------------
// MMA flash attention (unchanged from R6, ~280us).
// ---------------------------------------------------------------------------
#define ASTG 36864
#define AMAT 9216

__global__ __launch_bounds__(256, 1) void attn_mma()
{
    extern __shared__ __align__(16) char smem[];
    const uint32_t sm0 = (uint32_t)__cvta_generic_to_shared(smem);

    const int tid  = threadIdx.x;
    const int lane = tid & 31;
    const int wq   = tid >> 5;
    const int bh = blockIdx.y;
    const int q0 = blockIdx.x * 128;

    const __nv_bfloat16* Qhp = g_qh + (size_t)bh * NDh;
    const __nv_bfloat16* Qlp = g_ql + (size_t)bh * NDh;
    const __nv_bfloat16* Khp = g_kh + (size_t)bh * NDh;
    const __nv_bfloat16* Klp = g_kl + (size_t)bh * NDh;
    const __nv_bfloat16* Vhp = g_vh + (size_t)bh * NDh;
    const __nv_bfloat16* Vlp = g_vl + (size_t)bh * NDh;

    const uint32_t qbase = sm0 + ASTG;
#pragma unroll
    for (int u = 0; u < 8; u++) {
        const __nv_bfloat16* mp = (u < 4) ? Qhp : Qlp;
        int r = (u & 3) * 32 + (tid >> 3);
        int cc = tid & 7;
        CP_ASYNC16(qbase + (u >> 2) * (128 * 144) + r * 144 + cc * 16,
                   mp + (size_t)(q0 + r) * 64 + cc * 8);
    }
    CP_COMMIT();
    {
#pragma unroll
        for (int u = 0; u < 8; u++) {
            const __nv_bfloat16* mp = (u < 2) ? Khp : (u < 4) ? Klp
                                     : (u < 6) ? Vhp : Vlp;
            int r = (u & 1) * 32 + (tid >> 3);
            int cc = tid & 7;
            CP_ASYNC16(sm0 + (u >> 1) * AMAT + r * 144 + cc * 16,
                       mp + (size_t)r * 64 + cc * 8);
        }
        CP_COMMIT();
    }
    CP_WAIT1();
    __syncthreads();

    uint32_t qfh[4][4], qfl[4][4];
    {
        const int lr = lane & 7, lq = lane >> 3;
        uint32_t qa = qbase + (uint32_t)((wq * 16 + (lq & 1) * 8 + lr) * 144
                                         + (lq >> 1) * 16);
#pragma unroll
        for (int ks = 0; ks < 4; ks++) {
            LDSM4(qfh[ks][0], qfh[ks][1], qfh[ks][2], qfh[ks][3], qa + ks * 32);
            LDSM4(qfl[ks][0], qfl[ks][1], qfl[ks][2], qfl[ks][3],
                  qa + 128 * 144 + ks * 32);
        }
    }
    __syncthreads();

    float o[8][4];
    float mrow[2] = {-1e30f, -1e30f}, lrow[2] = {0.0f, 0.0f};
#pragma unroll
    for (int j = 0; j < 8; j++)
#pragma unroll
        for (int q = 0; q < 4; q++) o[j][q] = 0.0f;

    for (int t = 0; t < 16; t++) {
        if (t < 15) {
            uint32_t nb = sm0 + ((t + 1) & 1) * ASTG;
            int key0 = (t + 1) * 64;
#pragma unroll
            for (int u = 0; u < 8; u++) {
                const __nv_bfloat16* mp = (u < 2) ? Khp : (u < 4) ? Klp
                                         : (u < 6) ? Vhp : Vlp;
                int r = (u & 1) * 32 + (tid >> 3);
                int cc = tid & 7;
                CP_ASYNC16(nb + (u >> 1) * AMAT + r * 144 + cc * 16,
                           mp + (size_t)(key0 + r) * 64 + cc * 8);
            }
            CP_COMMIT();
            CP_WAIT1();
        } else {
            CP_WAIT0();
        }
        __syncthreads();

        const uint32_t st = sm0 + (t & 1) * ASTG;

        float s[8][4];
#pragma unroll
        for (int j = 0; j < 8; j++)
#pragma unroll
            for (int q = 0; q < 4; q++) s[j][q] = 0.0f;

        const uint32_t kaddr = st + (uint32_t)(((lane & 7) + ((lane >> 4) & 1) * 8) * 144
                                               + ((lane >> 3) & 1) * 16);
#pragma unroll
        for (int ks = 0; ks < 4; ks++) {
            uint32_t kh[4][4], kl[4][4];
#pragma unroll
            for (int jn2 = 0; jn2 < 4; jn2++) {
                uint32_t off = kaddr + (uint32_t)(jn2 * 16 * 144 + ks * 32);
                LDSM4(kh[jn2][0], kh[jn2][1], kh[jn2][2], kh[jn2][3], off);
                LDSM4(kl[jn2][0], kl[jn2][1], kl[jn2][2], kl[jn2][3], off + AMAT);
            }
#pragma unroll
            for (int jn2 = 0; jn2 < 4; jn2++) {
                MMA16816(s[2 * jn2],     qfh[ks], &kh[jn2][0]);
                MMA16816(s[2 * jn2],     qfh[ks], &kl[jn2][0]);
                MMA16816(s[2 * jn2],     qfl[ks], &kh[jn2][0]);
                MMA16816(s[2 * jn2 + 1], qfh[ks], &kh[jn2][2]);
                MMA16816(s[2 * jn2 + 1], qfh[ks], &kl[jn2][2]);
                MMA16816(s[2 * jn2 + 1], qfl[ks], &kh[jn2][2]);
            }
        }

#pragma unroll
        for (int r = 0; r < 2; r++) {
            float mx = -1e30f;
#pragma unroll
            for (int j = 0; j < 8; j++)
                mx = fmaxf(mx, fmaxf(s[j][2 * r], s[j][2 * r + 1]));
            mx = fmaxf(mx, __shfl_xor_sync(0xffffffffu, mx, 1));
            mx = fmaxf(mx, __shfl_xor_sync(0xffffffffu, mx, 2));
            float mnew = fmaxf(mrow[r], mx);
            float corr = __expf(mrow[r] - mnew);
            float sum = 0.0f;
#pragma unroll
            for (int j = 0; j < 8; j++) {
                s[j][2 * r]     = __expf(s[j][2 * r]     - mnew);
                s[j][2 * r + 1] = __expf(s[j][2 * r + 1] - mnew);
                sum += s[j][2 * r] + s[j][2 * r + 1];
            }
            sum += __shfl_xor_sync(0xffffffffu, sum, 1);
            sum += __shfl_xor_sync(0xffffffffu, sum, 2);
            lrow[r] = lrow[r] * corr + sum;
            mrow[r] = mnew;
#pragma unroll
            for (int j = 0; j < 8; j++) {
                o[j][2 * r]     *= corr;
                o[j][2 * r + 1] *= corr;
            }
        }

        const uint32_t vaddr = st + 2 * AMAT
            + (uint32_t)((lane & 15) * 144 + (lane >> 4) * 16);
#pragma unroll
        for (int ks2 = 0; ks2 < 4; ks2++) {
            uint32_t pah[4], pal[4];
            float* s0 = s[2 * ks2];
            float* s1 = s[2 * ks2 + 1];
            split2(s0[0], s0[1], pah[0], pal[0]);
            split2(s0[2], s0[3], pah[1], pal[1]);
            split2(s1[0], s1[1], pah[2], pal[2]);
            split2(s1[2], s1[3], pah[3], pal[3]);

            uint32_t vrow = vaddr + (uint32_t)(ks2 * 16 * 144);
#pragma unroll
            for (int jd2 = 0; jd2 < 4; jd2++) {
                uint32_t vh[4], vl[4];
                uint32_t off = vrow + (uint32_t)(jd2 * 32);
                LDSM4T(vh[0], vh[1], vh[2], vh[3], off);
                LDSM4T(vl[0], vl[1], vl[2], vl[3], off + AMAT);
                MMA16816(o[2 * jd2],     pah, &vh[0]);
                MMA16816(o[2 * jd2],     pah, &vl[0]);
                MMA16816(o[2 * jd2],     pal, &vh[0]);
                MMA16816(o[2 * jd2 + 1], pah, &vh[2]);
                MMA16816(o[2 * jd2 + 1], pah, &vl[2]);
                MMA16816(o[2 * jd2 + 1], pal, &vh[2]);
            }
        }
        __syncthreads();
    }

    const int b = bh >> 4, h = bh & 15;
    const int G = lane >> 2, T = lane & 3;
#pragma unroll
    for (int r = 0; r < 2; r++) {
        float inv = 1.0f / lrow[r];
        int row = q0 + wq * 16 + G + r * 8;
        size_t base = ((size_t)b * Nn + row) * Cc + h * 64;
#pragma unroll
        for (int jd = 0; jd < 8; jd++) {
            float v0 = o[jd][2 * r] * inv;
            float v1 = o[jd][2 * r + 1] * inv;
            int col = jd * 8 + 2 * T;
            uint32_t hp, lp;
            split2(v0, v1, hp, lp);
            *(uint32_t*)&g_aoh[base + col] = hp;
            *(uint32_t*)&g_aol[base + col] = lp;
        }
    }
}

// ---------------------------------------------------------------------------
extern "C" void kernel_launch(void* const* d_in, const int* in_sizes, int n_in,
                              void* d_out, int out_size)
{
    const float* x     = (const float*)d_in[0];
    const float* w_in  = (const float*)d_in[1];
    const float* b_in  = (const float*)d_in[2];
    const float* w_out = (const float*)d_in[3];
    const float* b_out = (const float*)d_in[4];
    float* out = (float*)d_out;

    cudaFuncSetAttribute(gemm_mma<0>,
                         cudaFuncAttributeMaxDynamicSharedMemorySize, GSMEM);
    cudaFuncSetAttribute(gemm_mma<1>,
                         cudaFuncAttributeMaxDynamicSharedMemorySize, GSMEM);
    cudaFuncSetAttribute(attn_mma,
                         cudaFuncAttributeMaxDynamicSharedMemorySize, 2 * ASTG);

    cvt_kernel<<<(Bb * Nn * Cc / 4 + 255) / 256, 256>>>((const float4*)x, 0, Bb * Nn * Cc / 4);
    cvt_kernel<<<(3 * Cc * Cc / 4 + 255) / 256, 256>>>((const float4*)w_in, 1, 3 * Cc * Cc / 4);
    cvt_kernel<<<(Cc * Cc / 4 + 255) / 256, 256>>>((const float4*)w_out, 2, Cc * Cc / 4);

    // QKV projection: 8192 x 3072 x 1024 -> q/k/v bf16 hi/lo (q pre-scaled)
    gemm_mma<0><<<dim3(24, 64), 256, GSMEM>>>(b_in, nullptr);
    // Attention: 8 q-tiles x 128 (b,h)
    attn_mma<<<dim3(8, 128), 256, 2 * ASTG>>>();
    // Output projection: 8192 x 1024 x 1024
    gemm_mma<1><<<dim3(8, 64), 256, GSMEM>>>(b_out, out);
}

// round 11
// speedup vs baseline: 1.5474x; 1.5474x over previous
#include <cuda_runtime.h>
#include <cuda_bf16.h>
#include <cstdint>

#define Bb 8
#define Nn 1024
#define Cc 1024
#define Hh 16
#define Dd 64
#define NDh (Nn * Dd)

// ---------------- scratch (device globals; allocation-free) ----------------
__device__ __align__(16) __nv_bfloat16 g_xh[Bb * Nn * Cc], g_xl[Bb * Nn * Cc];
__device__ __align__(16) __nv_bfloat16 g_wih[3 * Cc * Cc], g_wil[3 * Cc * Cc];
__device__ __align__(16) __nv_bfloat16 g_woh[Cc * Cc], g_wol[Cc * Cc];
__device__ __align__(16) __nv_bfloat16 g_qh[Bb * Hh * NDh], g_ql[Bb * Hh * NDh];
__device__ __align__(16) __nv_bfloat16 g_kh[Bb * Hh * NDh], g_kl[Bb * Hh * NDh];
__device__ __align__(16) __nv_bfloat16 g_vh[Bb * Hh * NDh], g_vl[Bb * Hh * NDh];
__device__ __align__(16) __nv_bfloat16 g_aoh[Bb * Nn * Cc], g_aol[Bb * Nn * Cc];

// ---------------------------- PTX helpers ----------------------------------
#define LDSM4(r0, r1, r2, r3, addr)                                          \
    asm volatile("ldmatrix.sync.aligned.m8n8.x4.shared.b16 {%0,%1,%2,%3},[%4];" \
                 : "=r"(r0), "=r"(r1), "=r"(r2), "=r"(r3) : "r"(addr))
#define LDSM4T(r0, r1, r2, r3, addr)                                         \
    asm volatile("ldmatrix.sync.aligned.m8n8.x4.trans.shared.b16 {%0,%1,%2,%3},[%4];" \
                 : "=r"(r0), "=r"(r1), "=r"(r2), "=r"(r3) : "r"(addr))
#define MMA16816(c, a, b)                                                    \
    asm volatile("mma.sync.aligned.m16n8k16.row.col.f32.bf16.bf16.f32 "      \
                 "{%0,%1,%2,%3},{%4,%5,%6,%7},{%8,%9},{%0,%1,%2,%3};"        \
                 : "+f"((c)[0]), "+f"((c)[1]), "+f"((c)[2]), "+f"((c)[3])    \
                 : "r"((a)[0]), "r"((a)[1]), "r"((a)[2]), "r"((a)[3]),       \
                   "r"((b)[0]), "r"((b)[1]))
#define CP_ASYNC16(dst, src)                                                 \
    asm volatile("cp.async.cg.shared.global [%0],[%1],16;" :: "r"(dst), "l"(src))
#define CP_COMMIT() asm volatile("cp.async.commit_group;")
#define CP_WAIT1()  asm volatile("cp.async.wait_group 1;")
#define CP_WAIT0()  asm volatile("cp.async.wait_group 0;")

__device__ __forceinline__ uint32_t packbf(float lo, float hi) {
    uint32_t r;
    asm("cvt.rn.bf16x2.f32 %0,%1,%2;" : "=r"(r) : "f"(hi), "f"(lo));
    return r;
}
__device__ __forceinline__ void split2(float v0, float v1,
                                       uint32_t& hi, uint32_t& lo) {
    __nv_bfloat16 h0 = __float2bfloat16(v0), h1 = __float2bfloat16(v1);
    hi = ((uint32_t)__bfloat16_as_ushort(h1) << 16) | __bfloat16_as_ushort(h0);
    lo = packbf(v0 - __bfloat162float(h0), v1 - __bfloat162float(h1));
}

// --------------- fp32 -> bf16 hi/lo split (single merged launch) -----------
#define N4X  (Bb * Nn * Cc / 4)
#define N4WI (3 * Cc * Cc / 4)
#define N4WO (Cc * Cc / 4)

__global__ __launch_bounds__(256) void cvt_all(const float4* __restrict__ x,
                                               const float4* __restrict__ wi,
                                               const float4* __restrict__ wo)
{
    int i = blockIdx.x * 256 + threadIdx.x;
    const float4* src;
    __nv_bfloat16 *hi, *lo;
    int j;
    if (i < N4X)               { src = x;  hi = g_xh;  lo = g_xl;  j = i; }
    else if (i < N4X + N4WI)   { src = wi; hi = g_wih; lo = g_wil; j = i - N4X; }
    else if (i < N4X + N4WI + N4WO)
                               { src = wo; hi = g_woh; lo = g_wol; j = i - N4X - N4WI; }
    else return;
    float4 f = src[j];
    uint32_t h01, l01, h23, l23;
    split2(f.x, f.y, h01, l01);
    split2(f.z, f.w, h23, l23);
    ((uint2*)hi)[j] = make_uint2(h01, h23);
    ((uint2*)lo)[j] = make_uint2(l01, l23);
}

// ---------------------------------------------------------------------------
// bf16x3 TN GEMM (HMMA): C[m,n] = sum_k A[m,k]*W[n,k] + bias[n]
// CTA tile 128x128, BK=32, 3-stage cp.async, ONE __syncthreads per chunk.
// SW64-style swizzle (64B rows, 16B unit ^= (row>>1)&3): 32KB/stage,
// 3 stages = 96KB -> 2 CTAs/SM. 8 warps (4m x 2n), warp tile 32x64.
// MMAs interleaved across 2 B-tiles: same-accumulator dep distance 8.
// ---------------------------------------------------------------------------
#define MATG 8192                    // 128 rows x 64 B
#define GSTG (4 * MATG)              // 32768 B / stage
#define GSMEM (3 * GSTG)             // 98304 B

#define SWOFF(row, unit) ((uint32_t)((row) * 64 + (((unit) ^ (((row) >> 1) & 3)) << 4)))

template <int EPI>
__device__ __forceinline__ void tg_load(uint32_t sbase, int bm, int bn,
                                        int k0, int tid)
{
    const __nv_bfloat16* Ah = (EPI == 0) ? g_xh : g_aoh;
    const __nv_bfloat16* Al = (EPI == 0) ? g_xl : g_aol;
    const __nv_bfloat16* Wh = (EPI == 0) ? g_wih : g_woh;
    const __nv_bfloat16* Wl = (EPI == 0) ? g_wil : g_wol;
#pragma unroll
    for (int u = 0; u < 2; u++) {
        int idx = u * 256 + tid;          // 0..511
        int row = idx >> 2, un = idx & 3;
        uint32_t soff = SWOFF(row, un);
        size_t ga = (size_t)(bm + row) * 1024 + k0 + un * 8;
        size_t gw = (size_t)(bn + row) * 1024 + k0 + un * 8;
        CP_ASYNC16(sbase + 0 * MATG + soff, Ah + ga);
        CP_ASYNC16(sbase + 1 * MATG + soff, Al + ga);
        CP_ASYNC16(sbase + 2 * MATG + soff, Wh + gw);
        CP_ASYNC16(sbase + 3 * MATG + soff, Wl + gw);
    }
}

template <int EPI>
__global__ __launch_bounds__(256, 2) void gemm_mma(const float* __restrict__ bias,
                                                   float* __restrict__ out)
{
    extern __shared__ __align__(16) char smem[];
    const uint32_t sm0 = (uint32_t)__cvta_generic_to_shared(smem);

    const int tid  = threadIdx.x;
    const int lane = tid & 31;
    const int wid  = tid >> 5;
    const int wm = (wid & 3) * 32;     // warp m offset (4 groups)
    const int wn = (wid >> 2) * 64;    // warp n offset (2 groups)
    const int bm = blockIdx.y * 128;
    const int bn = blockIdx.x * 128;

    // ldmatrix lane geometry under the SW64 swizzle
    const int lr = lane & 7, lq = lane >> 3;
    const int arow = wm + (lq & 1) * 8 + lr;            // + im*16 (sx invariant)
    const int sxA  = ((arow >> 1) & 3);
    const int aub  = (lq >> 1);                         // unit bit0; bit1 = ks
    const int brow = wn + (lane & 7) + ((lane >> 4) & 1) * 8;  // + jn2*16
    const int sxB  = ((brow >> 1) & 3);
    const int bub  = ((lane >> 3) & 1);

    float c[2][8][4];
#pragma unroll
    for (int im = 0; im < 2; im++)
#pragma unroll
        for (int jn = 0; jn < 8; jn++)
#pragma unroll
            for (int q = 0; q < 4; q++) c[im][jn][q] = 0.0f;

    tg_load<EPI>(sm0 + 0 * GSTG, bm, bn, 0, tid);
    CP_COMMIT();
    tg_load<EPI>(sm0 + 1 * GSTG, bm, bn, 32, tid);
    CP_COMMIT();

    for (int ch = 0; ch < 32; ch++) {
        if (ch < 31) CP_WAIT1(); else CP_WAIT0();
        __syncthreads();               // stage ch%3 ready; oldest buffer free

        if (ch < 30) {                 // prefetch ch+2 into buffer (ch+2)%3
            tg_load<EPI>(sm0 + ((ch + 2) % 3) * GSTG, bm, bn, (ch + 2) * 32, tid);
            CP_COMMIT();
        }

        const uint32_t st = sm0 + (ch % 3) * GSTG;
        const uint32_t tAh = st, tAl = st + MATG;
        const uint32_t tBh = st + 2 * MATG, tBl = st + 3 * MATG;

#pragma unroll
        for (int ks = 0; ks < 2; ks++) {
            const uint32_t aup = (uint32_t)((((ks << 1) | aub) ^ sxA) << 4);
            const uint32_t bup = (uint32_t)((((ks << 1) | bub) ^ sxB) << 4);
            uint32_t aH[2][4], aL[2][4];
#pragma unroll
            for (int im = 0; im < 2; im++) {
                uint32_t off = (uint32_t)((arow + im * 16) * 64) + aup;
                LDSM4(aH[im][0], aH[im][1], aH[im][2], aH[im][3], tAh + off);
                LDSM4(aL[im][0], aL[im][1], aL[im][2], aL[im][3], tAl + off);
            }
#pragma unroll
            for (int jp = 0; jp < 2; jp++) {           // B-tile pairs {0,1},{2,3}
                uint32_t bh[2][4], bl[2][4];
#pragma unroll
                for (int j = 0; j < 2; j++) {
                    int jn2 = jp * 2 + j;
                    uint32_t off = (uint32_t)((brow + jn2 * 16) * 64) + bup;
                    LDSM4(bh[j][0], bh[j][1], bh[j][2], bh[j][3], tBh + off);
                    LDSM4(bl[j][0], bl[j][1], bl[j][2], bl[j][3], tBl + off);
                }
                // 24 MMAs over 8 independent accumulators (dep distance 8)
#pragma unroll
                for (int j = 0; j < 2; j++)
#pragma unroll
                    for (int im = 0; im < 2; im++) {
                        MMA16816(c[im][2 * (jp * 2 + j)],     aH[im], &bh[j][0]);
                        MMA16816(c[im][2 * (jp * 2 + j) + 1], aH[im], &bh[j][2]);
                    }
#pragma unroll
                for (int j = 0; j < 2; j++)
#pragma unroll
                    for (int im = 0; im < 2; im++) {
                        MMA16816(c[im][2 * (jp * 2 + j)],     aH[im], &bl[j][0]);
                        MMA16816(c[im][2 * (jp * 2 + j) + 1], aH[im], &bl[j][2]);
                    }
#pragma unroll
                for (int j = 0; j < 2; j++)
#pragma unroll
                    for (int im = 0; im < 2; im++) {
                        MMA16816(c[im][2 * (jp * 2 + j)],     aL[im], &bh[j][0]);
                        MMA16816(c[im][2 * (jp * 2 + j) + 1], aL[im], &bh[j][2]);
                    }
            }
        }
    }

    // epilogue
#pragma unroll
    for (int im = 0; im < 2; im++) {
#pragma unroll
        for (int jn = 0; jn < 8; jn++) {
            int r0 = bm + wm + im * 16 + (lane >> 2);
            int cg = bn + wn + jn * 8 + 2 * (lane & 3);
            float b0 = bias[cg], b1 = bias[cg + 1];
#pragma unroll
            for (int half = 0; half < 2; half++) {
                int r = r0 + half * 8;
                float v0 = c[im][jn][half * 2 + 0] + b0;
                float v1 = c[im][jn][half * 2 + 1] + b1;
                if (EPI == 0) {
                    int b = r >> 10, nn = r & 1023;
                    int s = cg >> 10;
                    int h = (cg >> 6) & 15;
                    int d = cg & 63;
                    if (s == 0) { v0 *= 0.125f; v1 *= 0.125f; }  // fold QK scale
                    __nv_bfloat16 *hiA = (s == 0) ? g_qh : (s == 1) ? g_kh : g_vh;
                    __nv_bfloat16 *loA = (s == 0) ? g_ql : (s == 1) ? g_kl : g_vl;
                    size_t idx = (((size_t)b * Hh + h) * Nn + nn) * Dd + d;
                    uint32_t hp, lp;
                    split2(v0, v1, hp, lp);
                    *(uint32_t*)&hiA[idx] = hp;
                    *(uint32_t*)&loA[idx] = lp;
                } else {
                    *(float2*)&out[(size_t)r * 1024 + cg] = make_float2(v0, v1);
                }
            }
        }
    }
}

// ---------------------------------------------------------------------------
// MMA flash attention (unchanged; ~368 TF/s effective).
// ---------------------------------------------------------------------------
#define ASTG 36864
#define AMAT 9216

__global__ __launch_bounds__(256, 1) void attn_mma()
{
    extern __shared__ __align__(16) char smem[];
    const uint32_t sm0 = (uint32_t)__cvta_generic_to_shared(smem);

    const int tid  = threadIdx.x;
    const int lane = tid & 31;
    const int wq   = tid >> 5;
    const int bh = blockIdx.y;
    const int q0 = blockIdx.x * 128;

    const __nv_bfloat16* Qhp = g_qh + (size_t)bh * NDh;
    const __nv_bfloat16* Qlp = g_ql + (size_t)bh * NDh;
    const __nv_bfloat16* Khp = g_kh + (size_t)bh * NDh;
    const __nv_bfloat16* Klp = g_kl + (size_t)bh * NDh;
    const __nv_bfloat16* Vhp = g_vh + (size_t)bh * NDh;
    const __nv_bfloat16* Vlp = g_vl + (size_t)bh * NDh;

    const uint32_t qbase = sm0 + ASTG;
#pragma unroll
    for (int u = 0; u < 8; u++) {
        const __nv_bfloat16* mp = (u < 4) ? Qhp : Qlp;
        int r = (u & 3) * 32 + (tid >> 3);
        int cc = tid & 7;
        CP_ASYNC16(qbase + (u >> 2) * (128 * 144) + r * 144 + cc * 16,
                   mp + (size_t)(q0 + r) * 64 + cc * 8);
    }
    CP_COMMIT();
    {
#pragma unroll
        for (int u = 0; u < 8; u++) {
            const __nv_bfloat16* mp = (u < 2) ? Khp : (u < 4) ? Klp
                                     : (u < 6) ? Vhp : Vlp;
            int r = (u & 1) * 32 + (tid >> 3);
            int cc = tid & 7;
            CP_ASYNC16(sm0 + (u >> 1) * AMAT + r * 144 + cc * 16,
                       mp + (size_t)r * 64 + cc * 8);
        }
        CP_COMMIT();
    }
    CP_WAIT1();
    __syncthreads();

    uint32_t qfh[4][4], qfl[4][4];
    {
        const int lr = lane & 7, lq = lane >> 3;
        uint32_t qa = qbase + (uint32_t)((wq * 16 + (lq & 1) * 8 + lr) * 144
                                         + (lq >> 1) * 16);
#pragma unroll
        for (int ks = 0; ks < 4; ks++) {
            LDSM4(qfh[ks][0], qfh[ks][1], qfh[ks][2], qfh[ks][3], qa + ks * 32);
            LDSM4(qfl[ks][0], qfl[ks][1], qfl[ks][2], qfl[ks][3],
                  qa + 128 * 144 + ks * 32);
        }
    }
    __syncthreads();

    float o[8][4];
    float mrow[2] = {-1e30f, -1e30f}, lrow[2] = {0.0f, 0.0f};
#pragma unroll
    for (int j = 0; j < 8; j++)
#pragma unroll
        for (int q = 0; q < 4; q++) o[j][q] = 0.0f;

    for (int t = 0; t < 16; t++) {
        if (t < 15) {
            uint32_t nb = sm0 + ((t + 1) & 1) * ASTG;
            int key0 = (t + 1) * 64;
#pragma unroll
            for (int u = 0; u < 8; u++) {
                const __nv_bfloat16* mp = (u < 2) ? Khp : (u < 4) ? Klp
                                         : (u < 6) ? Vhp : Vlp;
                int r = (u & 1) * 32 + (tid >> 3);
                int cc = tid & 7;
                CP_ASYNC16(nb + (u >> 1) * AMAT + r * 144 + cc * 16,
                           mp + (size_t)(key0 + r) * 64 + cc * 8);
            }
            CP_COMMIT();
            CP_WAIT1();
        } else {
            CP_WAIT0();
        }
        __syncthreads();

        const uint32_t st = sm0 + (t & 1) * ASTG;

        float s[8][4];
#pragma unroll
        for (int j = 0; j < 8; j++)
#pragma unroll
            for (int q = 0; q < 4; q++) s[j][q] = 0.0f;

        const uint32_t kaddr = st + (uint32_t)(((lane & 7) + ((lane >> 4) & 1) * 8) * 144
                                               + ((lane >> 3) & 1) * 16);
#pragma unroll
        for (int ks = 0; ks < 4; ks++) {
            uint32_t kh[4][4], kl[4][4];
#pragma unroll
            for (int jn2 = 0; jn2 < 4; jn2++) {
                uint32_t off = kaddr + (uint32_t)(jn2 * 16 * 144 + ks * 32);
                LDSM4(kh[jn2][0], kh[jn2][1], kh[jn2][2], kh[jn2][3], off);
                LDSM4(kl[jn2][0], kl[jn2][1], kl[jn2][2], kl[jn2][3], off + AMAT);
            }
#pragma unroll
            for (int jn2 = 0; jn2 < 4; jn2++) {
                MMA16816(s[2 * jn2],     qfh[ks], &kh[jn2][0]);
                MMA16816(s[2 * jn2],     qfh[ks], &kl[jn2][0]);
                MMA16816(s[2 * jn2],     qfl[ks], &kh[jn2][0]);
                MMA16816(s[2 * jn2 + 1], qfh[ks], &kh[jn2][2]);
                MMA16816(s[2 * jn2 + 1], qfh[ks], &kl[jn2][2]);
                MMA16816(s[2 * jn2 + 1], qfl[ks], &kh[jn2][2]);
            }
        }

#pragma unroll
        for (int r = 0; r < 2; r++) {
            float mx = -1e30f;
#pragma unroll
            for (int j = 0; j < 8; j++)
                mx = fmaxf(mx, fmaxf(s[j][2 * r], s[j][2 * r + 1]));
            mx = fmaxf(mx, __shfl_xor_sync(0xffffffffu, mx, 1));
            mx = fmaxf(mx, __shfl_xor_sync(0xffffffffu, mx, 2));
            float mnew = fmaxf(mrow[r], mx);
            float corr = __expf(mrow[r] - mnew);
            float sum = 0.0f;
#pragma unroll
            for (int j = 0; j < 8; j++) {
                s[j][2 * r]     = __expf(s[j][2 * r]     - mnew);
                s[j][2 * r + 1] = __expf(s[j][2 * r + 1] - mnew);
                sum += s[j][2 * r] + s[j][2 * r + 1];
            }
            sum += __shfl_xor_sync(0xffffffffu, sum, 1);
            sum += __shfl_xor_sync(0xffffffffu, sum, 2);
            lrow[r] = lrow[r] * corr + sum;
            mrow[r] = mnew;
#pragma unroll
            for (int j = 0; j < 8; j++) {
                o[j][2 * r]     *= corr;
                o[j][2 * r + 1] *= corr;
            }
        }

        const uint32_t vaddr = st + 2 * AMAT
            + (uint32_t)((lane & 15) * 144 + (lane >> 4) * 16);
#pragma unroll
        for (int ks2 = 0; ks2 < 4; ks2++) {
            uint32_t pah[4], pal[4];
            float* s0 = s[2 * ks2];
            float* s1 = s[2 * ks2 + 1];
            split2(s0[0], s0[1], pah[0], pal[0]);
            split2(s0[2], s0[3], pah[1], pal[1]);
            split2(s1[0], s1[1], pah[2], pal[2]);
            split2(s1[2], s1[3], pah[3], pal[3]);

            uint32_t vrow = vaddr + (uint32_t)(ks2 * 16 * 144);
#pragma unroll
            for (int jd2 = 0; jd2 < 4; jd2++) {
                uint32_t vh[4], vl[4];
                uint32_t off = vrow + (uint32_t)(jd2 * 32);
                LDSM4T(vh[0], vh[1], vh[2], vh[3], off);
                LDSM4T(vl[0], vl[1], vl[2], vl[3], off + AMAT);
                MMA16816(o[2 * jd2],     pah, &vh[0]);
                MMA16816(o[2 * jd2],     pah, &vl[0]);
                MMA16816(o[2 * jd2],     pal, &vh[0]);
                MMA16816(o[2 * jd2 + 1], pah, &vh[2]);
                MMA16816(o[2 * jd2 + 1], pah, &vl[2]);
                MMA16816(o[2 * jd2 + 1], pal, &vh[2]);
            }
        }
        __syncthreads();
    }

    const int b = bh >> 4, h = bh & 15;
    const int G = lane >> 2, T = lane & 3;
#pragma unroll
    for (int r = 0; r < 2; r++) {
        float inv = 1.0f / lrow[r];
        int row = q0 + wq * 16 + G + r * 8;
        size_t base = ((size_t)b * Nn + row) * Cc + h * 64;
#pragma unroll
        for (int jd = 0; jd < 8; jd++) {
            float v0 = o[jd][2 * r] * inv;
            float v1 = o[jd][2 * r + 1] * inv;
            int col = jd * 8 + 2 * T;
            uint32_t hp, lp;
            split2(v0, v1, hp, lp);
            *(uint32_t*)&g_aoh[base + col] = hp;
            *(uint32_t*)&g_aol[base + col] = lp;
        }
    }
}

// ---------------------------------------------------------------------------
extern "C" void kernel_launch(void* const* d_in, const int* in_sizes, int n_in,
                              void* d_out, int out_size)
{
    const float* x     = (const float*)d_in[0];
    const float* w_in  = (const float*)d_in[1];
    const float* b_in  = (const float*)d_in[2];
    const float* w_out = (const float*)d_in[3];
    const float* b_out = (const float*)d_in[4];
    float* out = (float*)d_out;

    cudaFuncSetAttribute(gemm_mma<0>,
                         cudaFuncAttributeMaxDynamicSharedMemorySize, GSMEM);
    cudaFuncSetAttribute(gemm_mma<1>,
                         cudaFuncAttributeMaxDynamicSharedMemorySize, GSMEM);
    cudaFuncSetAttribute(attn_mma,
                         cudaFuncAttributeMaxDynamicSharedMemorySize, 2 * ASTG);

    // single merged hi/lo split launch (x, w_in, w_out)
    cvt_all<<<(N4X + N4WI + N4WO + 255) / 256, 256>>>(
        (const float4*)x, (const float4*)w_in, (const float4*)w_out);

    // QKV projection: 8192 x 3072 x 1024 -> q/k/v bf16 hi/lo (q pre-scaled)
    gemm_mma<0><<<dim3(24, 64), 256, GSMEM>>>(b_in, nullptr);
    // Attention: 8 q-tiles x 128 (b,h)
    attn_mma<<<dim3(8, 128), 256, 2 * ASTG>>>();
    // Output projection: 8192 x 1024 x 1024
    gemm_mma<1><<<dim3(8, 64), 256, GSMEM>>>(b_out, out);
}